// round 7
// baseline (speedup 1.0000x reference)
#include <cuda_runtime.h>
#include <cuda_bf16.h>
#include <cstdint>

typedef unsigned long long ull;

#define BSZ   256
#define LSEQ  2048
#define DD    128   // DIN == DOUT == 128

// ---------------------------------------------------------------------------
// Scratch for the three x-projections (U includes u_b, Gx includes g_b).
// ---------------------------------------------------------------------------
__device__ float d_U [BSZ * LSEQ * DD];
__device__ float d_Gx[BSZ * LSEQ * DD];
__device__ float d_Ax[BSZ * LSEQ * DD];

// ---------------------------------------------------------------------------
// f32x2 helpers (FFMA2: 2 fp32 FMA per instruction on sm_103a)
// ---------------------------------------------------------------------------
__device__ __forceinline__ ull pk2(float x, float y) {
    ull r;
    asm("mov.b64 %0, {%1, %2};" : "=l"(r) : "f"(x), "f"(y));
    return r;
}
__device__ __forceinline__ float2 upk2(ull v) {
    float2 f;
    asm("mov.b64 {%0, %1}, %2;" : "=f"(f.x), "=f"(f.y) : "l"(v));
    return f;
}
__device__ __forceinline__ ull ffma2(ull a, ull b, ull c) {
    ull d;
    asm("fma.rn.f32x2 %0, %1, %2, %3;" : "=l"(d) : "l"(a), "l"(b), "l"(c));
    return d;
}

// HW tanh (MUFU.TANH, sm_75+): single instruction, ~2^-11 rel err.
__device__ __forceinline__ float tanh_hw(float x) {
    float r;
    asm("tanh.approx.f32 %0, %1;" : "=f"(r) : "f"(x));
    return r;
}

__device__ __forceinline__ float tanhf_fast(float x) {
    float ax = fabsf(x);
    float e  = __expf(-2.0f * ax);
    float r  = __fdividef(1.0f - e, 1.0f + e);
    return copysignf(r, x);
}

// ---------------------------------------------------------------------------
// Projection GEMM (unchanged, protected win): C[row,o] = x[row,:]·W[o,:]+b
// ---------------------------------------------------------------------------
__global__ void __launch_bounds__(256, 1)
rwa_proj_kernel(const float* __restrict__ x,
                const float* __restrict__ u_w,
                const float* __restrict__ u_b,
                const float* __restrict__ g_w,
                const float* __restrict__ g_b,
                const float* __restrict__ a_w)
{
    extern __shared__ ull smem[];
    ull* Asm = smem;          // [128][64] float2 : Asm[m*64 + k2]
    ull* Bsm = smem + 8192;   // [128][64] float2 : Bsm[n*64 + (k2 ^ (n&15))]

    const int tid = threadIdx.x;
    const int tx  = tid & 15;     // -> n = tx + jj*16
    const int ty  = tid >> 4;     // -> m = ty + ii*16
    const int nt  = blockIdx.y;
    const int row0 = blockIdx.x * 128;

    const float* wsrc = (nt == 0) ? u_w : (nt == 1) ? g_w : a_w;
    const int    wpitch = (nt == 0) ? 128 : 256;

    {
        const float4* xp = (const float4*)(x + (size_t)row0 * DD);
        #pragma unroll
        for (int i = 0; i < 16; i++) {
            int idx = tid + i * 256;
            int r  = idx >> 5;
            int c4 = idx & 31;
            float4 v = xp[(size_t)r * 32 + c4];
            Asm[r * 64 + c4 * 2    ] = pk2(v.x, v.y);
            Asm[r * 64 + c4 * 2 + 1] = pk2(v.z, v.w);
        }
    }
    {
        #pragma unroll
        for (int i = 0; i < 16; i++) {
            int idx = tid + i * 256;
            int n  = idx >> 5;
            int c4 = idx & 31;
            const float4* wp = (const float4*)(wsrc + (size_t)n * wpitch);
            float4 v = wp[c4];
            int sw = n & 15;
            Bsm[n * 64 + ((c4 * 2    ) ^ sw)] = pk2(v.x, v.y);
            Bsm[n * 64 + ((c4 * 2 + 1) ^ sw)] = pk2(v.z, v.w);
        }
    }
    __syncthreads();

    ull acc[8][8];
    #pragma unroll
    for (int ii = 0; ii < 8; ii++)
        #pragma unroll
        for (int jj = 0; jj < 8; jj++) acc[ii][jj] = 0ull;

    #pragma unroll 4
    for (int k2 = 0; k2 < 64; k2++) {
        ull af[8], bf[8];
        #pragma unroll
        for (int ii = 0; ii < 8; ii++)
            af[ii] = Asm[(ty + ii * 16) * 64 + k2];
        #pragma unroll
        for (int jj = 0; jj < 8; jj++)
            bf[jj] = Bsm[(tx + jj * 16) * 64 + (k2 ^ tx)];
        #pragma unroll
        for (int ii = 0; ii < 8; ii++)
            #pragma unroll
            for (int jj = 0; jj < 8; jj++)
                acc[ii][jj] = ffma2(af[ii], bf[jj], acc[ii][jj]);
    }

    float bias[8];
    #pragma unroll
    for (int jj = 0; jj < 8; jj++) {
        int n = tx + jj * 16;
        bias[jj] = (nt == 0) ? u_b[n] : (nt == 1) ? g_b[n] : 0.0f;
    }
    float* dst = (nt == 0) ? d_U : (nt == 1) ? d_Gx : d_Ax;

    #pragma unroll
    for (int ii = 0; ii < 8; ii++) {
        size_t rbase = (size_t)(row0 + ty + ii * 16) * DD;
        #pragma unroll
        for (int jj = 0; jj < 8; jj++) {
            float2 s = upk2(acc[ii][jj]);
            dst[rbase + tx + jj * 16] = s.x + s.y + bias[jj];
        }
    }
}

// ---------------------------------------------------------------------------
// Recurrent kernel v4: 128 CTAs x 1024 threads (32 warps, occ 50%).
//   o = tid>>3 (output channel), q = tid&7 (K-eighth), mb = q&1.
//   Per-thread K-slice = 16 floats -> weights wg[8]+wa[8] = 32 regs; whole
//   kernel fits ~64 regs so 8 warps/SMSP hide the LDS/SHFL/MUFU latency that
//   the 4-warp version exposed (fma pipe was only 28.7% busy).
//   h in smem: [buf][batch][chunk(8)][20 floats]; 80B chunk stride puts the 8
//   chunk bases on 8 disjoint 4-bank groups (covers all 32 banks) ->
//   conflict-free LDS.128 with 4-way o-broadcast.
//   Reduction: 6 shfls (xor1 exchanges other-batch partials, xor2/xor4 fold).
// ---------------------------------------------------------------------------
__global__ void __launch_bounds__(1024, 1)
rwa_rec_kernel(const float* __restrict__ g_w,
               const float* __restrict__ a_w,
               const float* __restrict__ s0,
               float* __restrict__ out)
{
    __shared__ __align__(16) float hs[2][2][8][20];  // [buf][batch][chunk][16+4 pad]

    const int tid = threadIdx.x;
    const int o   = tid >> 3;
    const int q   = tid & 7;
    const int mb  = q & 1;          // batch this lane's epilogue handles

    // h-recurrence weight slice (cols 128+q*16 .. +16), in registers
    ull wg[8], wa[8];
    {
        const ull* gp = (const ull*)(g_w + (size_t)o * 256 + 128 + q * 16);
        const ull* ap = (const ull*)(a_w + (size_t)o * 256 + 128 + q * 16);
        #pragma unroll
        for (int j = 0; j < 8; j++) { wg[j] = gp[j]; wa[j] = ap[j]; }
    }

    // epilogue state for batch mb (4 lanes per (o,mb) hold identical copies)
    float num = 0.0f, den = 0.0f, amax = 1e-38f;
    const size_t idx0 = ((size_t)(blockIdx.x * 2 + mb)) * LSEQ * DD + o;

    // init h(-1) = tanh(s0) into buffer 0 (same value for both batches)
    if (q < 2) {
        hs[0][mb][o >> 4][o & 15] = tanhf_fast(s0[o]);
    }
    // current-step (t=0) inputs
    float cu = d_U[idx0], cg = d_Gx[idx0], ca = d_Ax[idx0];
    __syncthreads();

    for (int t = 0; t < LSEQ; t++) {
        // prefetch t+1 inputs (independent of h -> overlaps matvec + barrier)
        float nu = 0.0f, ng = 0.0f, na = 0.0f;
        if (t + 1 < LSEQ) {
            size_t id = idx0 + (size_t)(t + 1) * DD;
            nu = d_U[id]; ng = d_Gx[id]; na = d_Ax[id];
        }

        // ---- h-matvec partials: both batches, this thread's K-eighth ----
        const ulonglong2* h0p = (const ulonglong2*)&hs[t & 1][0][q][0];
        const ulonglong2* h1p = (const ulonglong2*)&hs[t & 1][1][q][0];
        ull aG0 = 0ull, aA0 = 0ull, aG1 = 0ull, aA1 = 0ull;
        #pragma unroll
        for (int j = 0; j < 4; j++) {
            ulonglong2 h0 = h0p[j];
            ulonglong2 h1 = h1p[j];
            aG0 = ffma2(wg[2*j  ], h0.x, aG0);
            aA0 = ffma2(wa[2*j  ], h0.x, aA0);
            aG1 = ffma2(wg[2*j  ], h1.x, aG1);
            aA1 = ffma2(wa[2*j  ], h1.x, aA1);
            aG0 = ffma2(wg[2*j+1], h0.y, aG0);
            aA0 = ffma2(wa[2*j+1], h0.y, aA0);
            aG1 = ffma2(wg[2*j+1], h1.y, aG1);
            aA1 = ffma2(wa[2*j+1], h1.y, aA1);
        }
        float2 s;
        s = upk2(aG0); float sG0 = s.x + s.y;
        s = upk2(aA0); float sA0 = s.x + s.y;
        s = upk2(aG1); float sG1 = s.x + s.y;
        s = upk2(aA1); float sA1 = s.x + s.y;

        // ---- reduction over q (8 lanes): 6 shfls ----
        // xor 1: exchange the OTHER batch's partial with mb-partner
        float sendG = mb ? sG0 : sG1;
        float sendA = mb ? sA0 : sA1;
        float rG = __shfl_xor_sync(0xffffffffu, sendG, 1);
        float rA = __shfl_xor_sync(0xffffffffu, sendA, 1);
        float myG = (mb ? sG1 : sG0) + rG;   // my batch, pair-folded
        float myA = (mb ? sA1 : sA0) + rA;
        // xor 2, xor 4: fold remaining K-slices (partners share mb)
        myG += __shfl_xor_sync(0xffffffffu, myG, 2);
        myA += __shfl_xor_sync(0xffffffffu, myA, 2);
        myG += __shfl_xor_sync(0xffffffffu, myG, 4);
        myA += __shfl_xor_sync(0xffffffffu, myA, 4);

        // ---- epilogue (every lane, batch mb) ----
        float g  = tanh_hw(cg + myG);
        float z  = cu * g;
        float a  = ca + myA;
        float m  = fmaxf(a, amax);
        float e  = __expf(m - amax);
        amax = m;
        num  = fmaf(z, e, num);
        den += e;
        float h = tanh_hw(__fdividef(num, den));

        if (q < 2) {
            hs[(t + 1) & 1][mb][o >> 4][o & 15] = h;
            out[idx0 + (size_t)t * DD] = h;
        }

        cu = nu; cg = ng; ca = na;
        __syncthreads();   // publish h(t) for step t+1
    }
}

// ---------------------------------------------------------------------------
// kernel_launch
// Input order (metadata): 0:x  1:s0  2:u_w  3:u_b  4:g_w  5:g_b  6:a_w
// ---------------------------------------------------------------------------
extern "C" void kernel_launch(void* const* d_in, const int* in_sizes, int n_in,
                              void* d_out, int out_size)
{
    const float* x   = (const float*)d_in[0];
    const float* s0  = (const float*)d_in[1];
    const float* u_w = (const float*)d_in[2];
    const float* u_b = (const float*)d_in[3];
    const float* g_w = (const float*)d_in[4];
    const float* g_b = (const float*)d_in[5];
    const float* a_w = (const float*)d_in[6];
    float* out = (float*)d_out;

    cudaFuncSetAttribute(rwa_proj_kernel,
                         cudaFuncAttributeMaxDynamicSharedMemorySize, 131072);

    dim3 pgrid((BSZ * LSEQ) / 128, 3, 1);
    rwa_proj_kernel<<<pgrid, 256, 131072>>>(x, u_w, u_b, g_w, g_b, a_w);

    rwa_rec_kernel<<<BSZ / 2, 1024>>>(g_w, a_w, s0, out);
}

// round 11
// speedup vs baseline: 1.7470x; 1.7470x over previous
#include <cuda_runtime.h>
#include <cuda_bf16.h>
#include <cstdint>

typedef unsigned long long ull;

#define BSZ   256
#define LSEQ  2048
#define DD    128   // DIN == DOUT == 128

// ---------------------------------------------------------------------------
// Scratch: projections (fp32) + pre-split bf16 weights (hi/lo).
// ---------------------------------------------------------------------------
__device__ float d_U [BSZ * LSEQ * DD];
__device__ float d_Gx[BSZ * LSEQ * DD];
__device__ float d_Ax[BSZ * LSEQ * DD];
__device__ __nv_bfloat16 d_Wh[3 * DD * DD];   // [m][o][d] K-major
__device__ __nv_bfloat16 d_Wl[3 * DD * DD];

// ---------------------------------------------------------------------------
// small helpers
// ---------------------------------------------------------------------------
__device__ __forceinline__ ull ffma2(ull a, ull b, ull c) {
    ull d;
    asm("fma.rn.f32x2 %0, %1, %2, %3;" : "=l"(d) : "l"(a), "l"(b), "l"(c));
    return d;
}
__device__ __forceinline__ float2 upk2(ull v) {
    float2 f;
    asm("mov.b64 {%0, %1}, %2;" : "=f"(f.x), "=f"(f.y) : "l"(v));
    return f;
}
__device__ __forceinline__ float tanh_hw(float x) {
    float r;
    asm("tanh.approx.f32 %0, %1;" : "=f"(r) : "f"(x));
    return r;
}
__device__ __forceinline__ float tanhf_fast(float x) {
    float ax = fabsf(x);
    float e  = __expf(-2.0f * ax);
    float r  = __fdividef(1.0f - e, 1.0f + e);
    return copysignf(r, x);
}
__device__ __forceinline__ uint32_t pack_bf2(float a, float b) {
    __nv_bfloat162 t = __floats2bfloat162_rn(a, b);
    return *(uint32_t*)&t;
}

// mma.sync m16n8k16 row.col f32.bf16.bf16.f32 (baseline PTX, legal at compute_103)
__device__ __forceinline__ void mma16816(float* c, const uint32_t* a, const uint32_t* b) {
    asm volatile(
        "mma.sync.aligned.m16n8k16.row.col.f32.bf16.bf16.f32 "
        "{%0,%1,%2,%3}, {%4,%5,%6,%7}, {%8,%9}, {%0,%1,%2,%3};"
        : "+f"(c[0]), "+f"(c[1]), "+f"(c[2]), "+f"(c[3])
        : "r"(a[0]), "r"(a[1]), "r"(a[2]), "r"(a[3]), "r"(b[0]), "r"(b[1]));
}

// ---------------------------------------------------------------------------
// Prep kernel: split weights into bf16 hi/lo (once, tiny).
//   m=0: u_w (pitch 128); m=1: g_w[:, :128] (pitch 256); m=2: a_w[:, :128]
// ---------------------------------------------------------------------------
__global__ void rwa_prep_kernel(const float* __restrict__ u_w,
                                const float* __restrict__ g_w,
                                const float* __restrict__ a_w)
{
    int idx = blockIdx.x * blockDim.x + threadIdx.x;
    if (idx >= 3 * DD * DD) return;
    int m = idx / (DD * DD);
    int r = idx - m * DD * DD;
    int o = r >> 7, d = r & 127;
    float w = (m == 0) ? u_w[o * 128 + d]
            : (m == 1) ? g_w[o * 256 + d]
                       : a_w[o * 256 + d];
    __nv_bfloat16 h = __float2bfloat16_rn(w);
    float res = w - __bfloat162float(h);
    d_Wh[idx] = h;
    d_Wl[idx] = __float2bfloat16_rn(res);
}

// ---------------------------------------------------------------------------
// Projection GEMM on tensor cores (HMMA via mma.sync), 3xBF16 split:
//   D = Ahi*Bhi + Ahi*Blo + Alo*Bhi  (fp32 accumulators)
// Per CTA: M=128 rows (b*L+t) x K=128, three N=128 outputs (U, Gx, Ax).
// 8 warps = 4(M) x 2(N); warp tile 32x64 = 2 x 8 m16n8k16 tiles.
// smem layout: row-major, 68 b32-words per row (stride 68 === 4 mod 32 ->
// fragment loads conflict-free).
// ---------------------------------------------------------------------------
#define PJ_STRIDE 68                       // b32 words per smem row
#define PJ_ROWB   (PJ_STRIDE * 4)          // 272 bytes
#define OFF_AH 0
#define OFF_AL (OFF_AH + 128 * PJ_ROWB)    // 34816
#define OFF_WH (OFF_AL + 128 * PJ_ROWB)    // 69632
#define OFF_WL (OFF_WH + 128 * PJ_ROWB)    // 104448
#define OFF_BIAS (OFF_WL + 128 * PJ_ROWB)  // 139264
#define PJ_SMEM (OFF_BIAS + 1024)          // 140288

__global__ void __launch_bounds__(256, 1)
rwa_proj_mma_kernel(const float* __restrict__ x,
                    const float* __restrict__ u_b,
                    const float* __restrict__ g_b)
{
    extern __shared__ char smem[];
    uint32_t* Ah = (uint32_t*)(smem + OFF_AH);
    uint32_t* Al = (uint32_t*)(smem + OFF_AL);
    uint32_t* Wh = (uint32_t*)(smem + OFF_WH);
    uint32_t* Wl = (uint32_t*)(smem + OFF_WL);
    float* bias_s = (float*)(smem + OFF_BIAS);

    const int tid = threadIdx.x;
    const int wid = tid >> 5;
    const int lid = tid & 31;
    const int g   = lid >> 2;      // group (row within fragment)
    const int tig = lid & 3;       // thread-in-group (k-pair / col-pair)
    const int wm  = wid & 3;       // warp M index (0..3) -> rows wm*32..+32
    const int wn  = wid >> 2;      // warp N index (0..1) -> cols wn*64..+64
    const int row0 = blockIdx.x * 128;

    if (tid < 128) {
        bias_s[tid]       = u_b[tid];
        bias_s[128 + tid] = g_b[tid];
    }

    // ---- load x tile (128x128 fp32), split hi/lo bf16, store to smem ----
    {
        const float4* xp = (const float4*)(x + (size_t)row0 * DD);
        #pragma unroll
        for (int i = 0; i < 16; i++) {
            int f   = tid + i * 256;       // float4 index; 32 per row
            int row = f >> 5;
            int c4  = f & 31;
            float4 v = xp[f];
            __nv_bfloat16 h0 = __float2bfloat16_rn(v.x);
            __nv_bfloat16 h1 = __float2bfloat16_rn(v.y);
            __nv_bfloat16 h2 = __float2bfloat16_rn(v.z);
            __nv_bfloat16 h3 = __float2bfloat16_rn(v.w);
            int idx = row * PJ_STRIDE + c4 * 2;
            Ah[idx]     = pack_bf2(__bfloat162float(h0), __bfloat162float(h1));
            Ah[idx + 1] = pack_bf2(__bfloat162float(h2), __bfloat162float(h3));
            Al[idx]     = pack_bf2(v.x - __bfloat162float(h0),
                                   v.y - __bfloat162float(h1));
            Al[idx + 1] = pack_bf2(v.z - __bfloat162float(h2),
                                   v.w - __bfloat162float(h3));
        }
    }
    __syncthreads();

    for (int m = 0; m < 3; m++) {
        // ---- load weight tile m (hi/lo bf16) into smem ----
        {
            const uint4* wh = (const uint4*)(d_Wh + m * DD * DD);
            const uint4* wl = (const uint4*)(d_Wl + m * DD * DD);
            #pragma unroll
            for (int i = 0; i < 8; i++) {
                int f  = tid + i * 256;    // uint4 = 8 bf16; 16 per row
                int n  = f >> 4;
                int j4 = f & 15;
                int idx = n * PJ_STRIDE + j4 * 4;   // byte addr 16-aligned
                *(uint4*)(Wh + idx) = wh[f];
                *(uint4*)(Wl + idx) = wl[f];
            }
        }
        __syncthreads();

        float acc[2][8][4];
        #pragma unroll
        for (int i = 0; i < 2; i++)
            #pragma unroll
            for (int j = 0; j < 8; j++)
                #pragma unroll
                for (int c = 0; c < 4; c++) acc[i][j][c] = 0.0f;

        #pragma unroll
        for (int pass = 0; pass < 3; pass++) {
            const uint32_t* Ap = (pass == 2) ? Al : Ah;
            const uint32_t* Bp = (pass == 1) ? Wl : Wh;
            #pragma unroll
            for (int ks = 0; ks < 8; ks++) {
                const int kp0 = ks * 8;
                uint32_t a[2][4];
                #pragma unroll
                for (int i = 0; i < 2; i++) {
                    int r = wm * 32 + i * 16 + g;
                    a[i][0] = Ap[r * PJ_STRIDE + kp0 + tig];
                    a[i][1] = Ap[(r + 8) * PJ_STRIDE + kp0 + tig];
                    a[i][2] = Ap[r * PJ_STRIDE + kp0 + 4 + tig];
                    a[i][3] = Ap[(r + 8) * PJ_STRIDE + kp0 + 4 + tig];
                }
                uint32_t b[8][2];
                #pragma unroll
                for (int j = 0; j < 8; j++) {
                    int n = wn * 64 + j * 8 + g;
                    b[j][0] = Bp[n * PJ_STRIDE + kp0 + tig];
                    b[j][1] = Bp[n * PJ_STRIDE + kp0 + 4 + tig];
                }
                #pragma unroll
                for (int i = 0; i < 2; i++)
                    #pragma unroll
                    for (int j = 0; j < 8; j++)
                        mma16816(acc[i][j], a[i], b[j]);
            }
        }

        // ---- bias + store ----
        float* dst = (m == 0) ? d_U : (m == 1) ? d_Gx : d_Ax;
        #pragma unroll
        for (int i = 0; i < 2; i++) {
            #pragma unroll
            for (int j = 0; j < 8; j++) {
                int r = row0 + wm * 32 + i * 16 + g;
                int c = wn * 64 + j * 8 + tig * 2;
                float bx = 0.0f, by = 0.0f;
                if (m < 2) {
                    bx = bias_s[m * 128 + c];
                    by = bias_s[m * 128 + c + 1];
                }
                float2 v0 = make_float2(acc[i][j][0] + bx, acc[i][j][1] + by);
                float2 v1 = make_float2(acc[i][j][2] + bx, acc[i][j][3] + by);
                *(float2*)(dst + (size_t)r * DD + c)       = v0;
                *(float2*)(dst + (size_t)(r + 8) * DD + c) = v1;
            }
        }
        __syncthreads();   // before overwriting W tile
    }
}

// ---------------------------------------------------------------------------
// Recurrent kernel (exact R5 version — best measured 1722us):
// 128 CTAs x 512 threads, o=tid>>2, q=tid&3, mb=q&1.
// ---------------------------------------------------------------------------
__global__ void __launch_bounds__(512, 1)
rwa_rec_kernel(const float* __restrict__ g_w,
               const float* __restrict__ a_w,
               const float* __restrict__ s0,
               float* __restrict__ out)
{
    __shared__ float hs[2][2][4][36];   // [buf][batch][chunk][32 + 4 pad]

    const int tid = threadIdx.x;
    const int o   = tid >> 2;
    const int q   = tid & 3;
    const int mb  = q & 1;

    ull wg[16], wa[16];
    {
        const ull* gp = (const ull*)(g_w + (size_t)o * 256 + 128 + q * 32);
        const ull* ap = (const ull*)(a_w + (size_t)o * 256 + 128 + q * 32);
        #pragma unroll
        for (int j = 0; j < 16; j++) { wg[j] = gp[j]; wa[j] = ap[j]; }
    }

    float num = 0.0f, den = 0.0f, amax = 1e-38f;
    const size_t idx0 = ((size_t)(blockIdx.x * 2 + mb)) * LSEQ * DD + o;

    if (q < 2) {
        hs[0][mb][o >> 5][o & 31] = tanhf_fast(s0[o]);
    }
    float cu = d_U[idx0], cg = d_Gx[idx0], ca = d_Ax[idx0];
    __syncthreads();

    for (int t = 0; t < LSEQ; t++) {
        float nu = 0.0f, ng = 0.0f, na = 0.0f;
        if (t + 1 < LSEQ) {
            size_t id = idx0 + (size_t)(t + 1) * DD;
            nu = d_U[id]; ng = d_Gx[id]; na = d_Ax[id];
        }

        const ulonglong2* h0p = (const ulonglong2*)&hs[t & 1][0][q][0];
        const ulonglong2* h1p = (const ulonglong2*)&hs[t & 1][1][q][0];
        ull aG0 = 0ull, aA0 = 0ull, aG1 = 0ull, aA1 = 0ull;
        #pragma unroll
        for (int j = 0; j < 8; j++) {
            ulonglong2 h0 = h0p[j];
            ulonglong2 h1 = h1p[j];
            aG0 = ffma2(wg[2*j  ], h0.x, aG0);
            aA0 = ffma2(wa[2*j  ], h0.x, aA0);
            aG1 = ffma2(wg[2*j  ], h1.x, aG1);
            aA1 = ffma2(wa[2*j  ], h1.x, aA1);
            aG0 = ffma2(wg[2*j+1], h0.y, aG0);
            aA0 = ffma2(wa[2*j+1], h0.y, aA0);
            aG1 = ffma2(wg[2*j+1], h1.y, aG1);
            aA1 = ffma2(wa[2*j+1], h1.y, aA1);
        }
        float2 s;
        s = upk2(aG0); float sG0 = s.x + s.y;
        s = upk2(aA0); float sA0 = s.x + s.y;
        s = upk2(aG1); float sG1 = s.x + s.y;
        s = upk2(aA1); float sA1 = s.x + s.y;

        float sendG = mb ? sG0 : sG1;
        float sendA = mb ? sA0 : sA1;
        float rG = __shfl_xor_sync(0xffffffffu, sendG, 1);
        float rA = __shfl_xor_sync(0xffffffffu, sendA, 1);
        float myG = (mb ? sG1 : sG0) + rG;
        float myA = (mb ? sA1 : sA0) + rA;
        myG += __shfl_xor_sync(0xffffffffu, myG, 2);
        myA += __shfl_xor_sync(0xffffffffu, myA, 2);

        float g  = tanh_hw(cg + myG);
        float z  = cu * g;
        float a  = ca + myA;
        float m  = fmaxf(a, amax);
        float e  = __expf(m - amax);
        amax = m;
        num  = fmaf(z, e, num);
        den += e;
        float h = tanh_hw(__fdividef(num, den));

        if (q < 2) {
            hs[(t + 1) & 1][mb][o >> 5][o & 31] = h;
            out[idx0 + (size_t)t * DD] = h;
        }

        cu = nu; cg = ng; ca = na;
        __syncthreads();
    }
}

// ---------------------------------------------------------------------------
// kernel_launch
// Input order (metadata): 0:x  1:s0  2:u_w  3:u_b  4:g_w  5:g_b  6:a_w
// ---------------------------------------------------------------------------
extern "C" void kernel_launch(void* const* d_in, const int* in_sizes, int n_in,
                              void* d_out, int out_size)
{
    const float* x   = (const float*)d_in[0];
    const float* s0  = (const float*)d_in[1];
    const float* u_w = (const float*)d_in[2];
    const float* u_b = (const float*)d_in[3];
    const float* g_w = (const float*)d_in[4];
    const float* g_b = (const float*)d_in[5];
    const float* a_w = (const float*)d_in[6];
    float* out = (float*)d_out;

    // 1) split weights to bf16 hi/lo
    rwa_prep_kernel<<<(3 * DD * DD + 255) / 256, 256>>>(u_w, g_w, a_w);

    // 2) projections on tensor cores (mma.sync bf16, 3-pass split)
    cudaFuncSetAttribute(rwa_proj_mma_kernel,
                         cudaFuncAttributeMaxDynamicSharedMemorySize, PJ_SMEM);
    rwa_proj_mma_kernel<<<(BSZ * LSEQ) / 128, 256, PJ_SMEM>>>(x, u_b, g_b);

    // 3) recurrence
    rwa_rec_kernel<<<BSZ / 2, 512>>>(g_w, a_w, s0, out);
}